// round 11
// baseline (speedup 1.0000x reference)
#include <cuda_runtime.h>

// Problem constants (from reference_code)
#define Hn    50000
#define INn   50000
#define NNZn  800000
#define Bn    8
#define Tn    32

#define NB    ((Hn + 255) / 256)   // 196 scan blocks per matrix
#define SP    768                  // smem hh-pair staging capacity per block

// ---------------- device scratch (static globals; no runtime allocation) ----
__device__ float g_xT[(size_t)Tn * INn * Bn];      // x transposed -> (T, IN, B)
__device__ float g_h[2][Hn * Bn];                  // ping-pong hidden state (H, B)
__device__ int   g_rowptr[2][Hn + 1];              // [0]=hh, [1]=ih
__device__ int   g_cnt[2][Hn];
__device__ int   g_cur[2][Hn];
__device__ int   g_bsum[2][256];
__device__ int2  g_pairs[2][NNZn];                 // {col, float_as_int(val)}

// ---------------- preprocessing -------------------------------------------

__global__ void init_kernel() {
    int i = blockIdx.x * blockDim.x + threadIdx.x;
    if (i < Hn * Bn) g_h[0][i] = 0.0f;
    if (i < Hn) { g_cnt[0][i] = 0; g_cnt[1][i] = 0; }
}

// fused histogram over both matrices (gridDim.y selects matrix)
__global__ void hist_kernel(const int* __restrict__ hh_idx,
                            const int* __restrict__ ih_idx) {
    int j = blockIdx.x * blockDim.x + threadIdx.x;
    int m = blockIdx.y;
    if (j >= NNZn) return;
    const int* rows = m ? ih_idx : hh_idx;
    atomicAdd(&g_cnt[m][rows[j]], 1);
}

// phase 1: per-block inclusive scan of 256 counts
__global__ void scan1_kernel() {
    int m = blockIdx.y;
    int i = blockIdx.x * 256 + threadIdx.x;
    int v = (i < Hn) ? g_cnt[m][i] : 0;
    int lane = threadIdx.x & 31, w = threadIdx.x >> 5;
    int x = v;
#pragma unroll
    for (int o = 1; o < 32; o <<= 1) {
        int y = __shfl_up_sync(~0u, x, o);
        if (lane >= o) x += y;
    }
    __shared__ int wsum[8];
    if (lane == 31) wsum[w] = x;
    __syncthreads();
    if (w == 0 && lane < 8) {
        int y = wsum[lane];
#pragma unroll
        for (int o = 1; o < 8; o <<= 1) {
            int z = __shfl_up_sync(0xffu, y, o);
            if (lane >= o) y += z;
        }
        wsum[lane] = y;
    }
    __syncthreads();
    int incl = x + (w > 0 ? wsum[w - 1] : 0);
    if (i < Hn) g_rowptr[m][i] = incl - v;          // local exclusive
    if (threadIdx.x == 255) g_bsum[m][blockIdx.x] = incl;
}

// phase 2: scan the (<=256) block sums
__global__ void scan2_kernel() {
    int m = blockIdx.y;
    int t = threadIdx.x;
    int v = (t < NB) ? g_bsum[m][t] : 0;
    int lane = t & 31, w = t >> 5;
    int x = v;
#pragma unroll
    for (int o = 1; o < 32; o <<= 1) {
        int y = __shfl_up_sync(~0u, x, o);
        if (lane >= o) x += y;
    }
    __shared__ int wsum[8];
    if (lane == 31) wsum[w] = x;
    __syncthreads();
    if (w == 0 && lane < 8) {
        int y = wsum[lane];
#pragma unroll
        for (int o = 1; o < 8; o <<= 1) {
            int z = __shfl_up_sync(0xffu, y, o);
            if (lane >= o) y += z;
        }
        wsum[lane] = y;
    }
    __syncthreads();
    int incl = x + (w > 0 ? wsum[w - 1] : 0);
    if (t < NB) g_bsum[m][t] = incl - v;
    if (t == 255) g_rowptr[m][Hn] = incl;           // total nnz
}

// phase 3: add block offsets; materialize rowptr + scatter cursor
__global__ void scan3_kernel() {
    int m = blockIdx.y;
    int i = blockIdx.x * 256 + threadIdx.x;
    if (i >= Hn) return;
    int r = g_rowptr[m][i] + g_bsum[m][blockIdx.x];
    g_rowptr[m][i] = r;
    g_cur[m][i]    = r;
}

// fused scatter into CSR pair arrays (gridDim.y selects matrix)
__global__ void scatter_kernel(const int* __restrict__ hh_idx,
                               const float* __restrict__ hh_vals,
                               const int* __restrict__ ih_idx,
                               const float* __restrict__ ih_vals) {
    int j = blockIdx.x * blockDim.x + threadIdx.x;
    int m = blockIdx.y;
    if (j >= NNZn) return;
    const int*   idx  = m ? ih_idx  : hh_idx;
    const float* vals = m ? ih_vals : hh_vals;
    int r = idx[j];
    int c = idx[NNZn + j];
    int p = atomicAdd(&g_cur[m][r], 1);
    g_pairs[m][p] = make_int2(c, __float_as_int(vals[j]));
}

// x (B, T, IN) -> g_xT (T, IN, B)
__global__ void transpose_kernel(const float* __restrict__ x) {
    int idx = blockIdx.x * blockDim.x + threadIdx.x;   // over T*IN
    if (idx >= Tn * INn) return;
    int t = idx / INn;
    int c = idx - t * INn;
    float v[Bn];
#pragma unroll
    for (int b = 0; b < Bn; ++b)
        v[b] = x[(size_t)b * Tn * INn + (size_t)t * INn + c];
    float4* dst = reinterpret_cast<float4*>(&g_xT[(size_t)idx * Bn]);
    dst[0] = make_float4(v[0], v[1], v[2], v[3]);
    dst[1] = make_float4(v[4], v[5], v[6], v[7]);
}

// ---------------- main compute ---------------------------------------------

// One fused recurrence step with ih-spmm folded into the PDL prologue.
//   pre  = bias[g] + ih@x_t        (h-INDEPENDENT: runs before gridsync,
//                                   overlapping the previous step)
//   h    = tanh(pre + hh@h_prev)   (after gridsync)
// Trigger fires at kernel ENTRY: the downstream prologue only touches
// step-invariant data (pairs/rowptr/xT/bias), so the only h-dependence is
// guarded by cudaGridDependencySynchronize() (full upstream completion).
template <bool LAST>
__global__ void __launch_bounds__(256)
step_kernel(const float* __restrict__ hprev,
            float* __restrict__ hnext,
            float* __restrict__ out_t,     // d_out + t*H
            const float* __restrict__ bias,
            int t) {
    __shared__ int2 s_pairs[SP];

    cudaTriggerProgrammaticLaunchCompletion();   // let the next step launch NOW

    const int g = blockIdx.x * 32 + (threadIdx.x >> 3);
    const int b = threadIdx.x & 7;
    const bool valid = g < Hn;

    // ---- h-independent prologue ----
    // stage this block's hh pairs into smem
    const int row0 = blockIdx.x * 32;
    const int row1 = (row0 + 32 < Hn) ? row0 + 32 : Hn;
    const int base = g_rowptr[0][row0];
    const int nnzb = g_rowptr[0][row1] - base;
    const int stage = nnzb < SP ? nnzb : SP;
    for (int i = threadIdx.x; i < stage; i += 256)
        s_pairs[i] = g_pairs[0][base + i];

    float acc = 0.0f;
    int jb = 0, je = 0;
    if (valid) {
        acc = bias[g];
        // ih contribution for timestep t (x is constant input)
        int ib = g_rowptr[1][g];
        int ie = g_rowptr[1][g + 1];
        const float* xt = g_xT + (size_t)t * INn * Bn;
        for (int j = ib; j < ie; ++j) {
            int2 p = __ldg(&g_pairs[1][j]);
            acc += __int_as_float(p.y) * xt[p.x * Bn + b];
        }
        jb = g_rowptr[0][g];
        je = g_rowptr[0][g + 1];
    }
    __syncthreads();

    // ---- wait for the previous step's h writes ----
    cudaGridDependencySynchronize();

    if (valid) {
        for (int j = jb; j < je; ++j) {
            int lj = j - base;
            int2 p = (lj < SP) ? s_pairs[lj] : g_pairs[0][j];
            acc += __int_as_float(p.y) * hprev[p.x * Bn + b];
        }
        float hv = tanhf(acc);
        if (!LAST) hnext[g * Bn + b] = hv;
        out_t[(size_t)b * Tn * Hn + g] = hv;   // out layout (B, T, H)
    }
}

// ---------------- launch ----------------------------------------------------

extern "C" void kernel_launch(void* const* d_in, const int* in_sizes, int n_in,
                              void* d_out, int out_size) {
    const float* x        = (const float*)d_in[0];   // (B, T, IN)
    const float* hh_vals  = (const float*)d_in[1];   // (NNZ,)
    const float* hh_bias  = (const float*)d_in[2];   // (H, 1)
    const float* ih_vals  = (const float*)d_in[3];   // (NNZ,)
    const int*   hh_idx   = (const int*)d_in[4];     // (2, NNZ): rows then cols
    const int*   ih_idx   = (const int*)d_in[5];     // (2, NNZ)
    float*       out      = (float*)d_out;           // (B, T, H)

    float* h_p;
    cudaGetSymbolAddress((void**)&h_p, g_h);

    const int TPB = 256;

    // 1) init counters + h0
    init_kernel<<<(Hn * Bn + TPB - 1) / TPB, TPB>>>();

    // 2) fused histograms
    dim3 hg((NNZn + TPB - 1) / TPB, 2);
    hist_kernel<<<hg, TPB>>>(hh_idx, ih_idx);

    // 3) hierarchical scans -> rowptr + cursor (both matrices at once)
    dim3 sg(NB, 2);
    scan1_kernel<<<sg, 256>>>();
    scan2_kernel<<<dim3(1, 2), 256>>>();
    scan3_kernel<<<sg, 256>>>();

    // 4) fused scatter into CSR pair arrays
    scatter_kernel<<<hg, TPB>>>(hh_idx, hh_vals, ih_idx, ih_vals);

    // 5) transpose x -> (T, IN, B)  (must complete before step 0's prologue;
    //    step 0 has no explicit trigger upstream, so PDL launches it only
    //    after transpose fully completes — safe)
    transpose_kernel<<<(Tn * INn + TPB - 1) / TPB, TPB>>>(x);

    // 6) sequential recurrence: 32 fused (ih + hh + tanh) steps, PDL-chained
    const int step_grid = (Hn + 31) / 32;        // 1563 blocks

    cudaLaunchAttribute attrs[1];
    attrs[0].id = cudaLaunchAttributeProgrammaticStreamSerialization;
    attrs[0].val.programmaticStreamSerializationAllowed = 1;

    cudaLaunchConfig_t cfg = {};
    cfg.gridDim  = dim3(step_grid, 1, 1);
    cfg.blockDim = dim3(256, 1, 1);
    cfg.dynamicSmemBytes = 0;
    cfg.stream = 0;                              // legacy default stream
    cfg.attrs = attrs;
    cfg.numAttrs = 1;

    for (int t = 0; t < Tn; ++t) {
        const float* hprev = h_p + (size_t)(t & 1) * Hn * Bn;
        float*       hnext = h_p + (size_t)((t + 1) & 1) * Hn * Bn;
        float*       outt  = out + (size_t)t * Hn;
        if (t + 1 < Tn)
            cudaLaunchKernelEx(&cfg, step_kernel<false>, hprev, hnext, outt,
                               hh_bias, t);
        else
            cudaLaunchKernelEx(&cfg, step_kernel<true>,  hprev, hnext, outt,
                               hh_bias, t);
    }
}